// round 1
// baseline (speedup 1.0000x reference)
#include <cuda_runtime.h>
#include <cuda_bf16.h>
#include <math.h>

// Problem constants
#define B_  2
#define S_  2048
#define D_  1024
#define H_  16
#define HD_ 64
#define M_  (B_ * S_)           // 4096 rows for projection GEMMs

// ---------------- scratch (static device globals; no runtime alloc) --------
__device__ float g_q[(size_t)B_ * S_ * D_];
__device__ float g_k[(size_t)B_ * S_ * D_];
__device__ float g_v[(size_t)B_ * S_ * D_];
__device__ float g_attn[(size_t)B_ * S_ * D_];

// ---------------- SGEMM: C[M,N] = A[M,K] * W[N,K]^T + bias[N] --------------
// 128x128 block tile, BK=8, 256 threads, 8x8 per-thread micro tile.
#define BM 128
#define BN 128
#define BKK 8

__global__ __launch_bounds__(256, 2)
void sgemm_bias_nt(const float* __restrict__ A, const float* __restrict__ W,
                   const float* __restrict__ bias, float* __restrict__ C,
                   int M, int N, int K) {
    __shared__ float As[BKK][BM];
    __shared__ float Ws[BKK][BN];

    const int tid = threadIdx.x;
    const int block_row = blockIdx.y * BM;
    const int block_col = blockIdx.x * BN;

    // Global->smem load mapping: 2 threads per row, one float4 each (BK=8)
    const int a_row  = tid >> 1;          // 0..127
    const int a_col4 = (tid & 1) << 2;    // 0 or 4

    const int ty = tid >> 4;              // 0..15
    const int tx = tid & 15;              // 0..15
    const int r0 = ty * 8;
    const int c0 = tx * 8;

    float acc[8][8];
#pragma unroll
    for (int i = 0; i < 8; ++i)
#pragma unroll
        for (int j = 0; j < 8; ++j) acc[i][j] = 0.0f;

    const float* Aptr = A + (size_t)(block_row + a_row) * K + a_col4;
    const float* Wptr = W + (size_t)(block_col + a_row) * K + a_col4;

    for (int k0 = 0; k0 < K; k0 += BKK) {
        float4 av = *(const float4*)(Aptr + k0);
        float4 wv = *(const float4*)(Wptr + k0);

        __syncthreads();   // previous iteration done reading smem
        As[a_col4 + 0][a_row] = av.x;
        As[a_col4 + 1][a_row] = av.y;
        As[a_col4 + 2][a_row] = av.z;
        As[a_col4 + 3][a_row] = av.w;
        Ws[a_col4 + 0][a_row] = wv.x;
        Ws[a_col4 + 1][a_row] = wv.y;
        Ws[a_col4 + 2][a_row] = wv.z;
        Ws[a_col4 + 3][a_row] = wv.w;
        __syncthreads();

#pragma unroll
        for (int kk = 0; kk < BKK; ++kk) {
            float a[8], b[8];
            float4 a0 = *(const float4*)&As[kk][r0];
            float4 a1 = *(const float4*)&As[kk][r0 + 4];
            float4 b0 = *(const float4*)&Ws[kk][c0];
            float4 b1 = *(const float4*)&Ws[kk][c0 + 4];
            a[0]=a0.x; a[1]=a0.y; a[2]=a0.z; a[3]=a0.w;
            a[4]=a1.x; a[5]=a1.y; a[6]=a1.z; a[7]=a1.w;
            b[0]=b0.x; b[1]=b0.y; b[2]=b0.z; b[3]=b0.w;
            b[4]=b1.x; b[5]=b1.y; b[6]=b1.z; b[7]=b1.w;
#pragma unroll
            for (int i = 0; i < 8; ++i)
#pragma unroll
                for (int j = 0; j < 8; ++j)
                    acc[i][j] = fmaf(a[i], b[j], acc[i][j]);
        }
    }

    // epilogue + bias
#pragma unroll
    for (int i = 0; i < 8; ++i) {
        float* crow = C + (size_t)(block_row + r0 + i) * N + block_col + c0;
#pragma unroll
        for (int j = 0; j < 8; ++j) {
            crow[j] = acc[i][j] + bias[block_col + c0 + j];
        }
    }
}

// ---------------- flash attention (fp32, online softmax) -------------------
// One CTA: 64 query rows of one (b, h). Streams 64-row K/V tiles.
// 256 threads as 16x16; each thread owns a 4x4 micro tile.
#define BQ 64
#define BKT 64

__global__ __launch_bounds__(256)
void flash_attn_f32(const float* __restrict__ Q, const float* __restrict__ K,
                    const float* __restrict__ V, const int* __restrict__ mask,
                    float* __restrict__ O) {
    extern __shared__ float sm[];
    float* Qs    = sm;                       // [BQ][HD]          4096
    float* Kst   = Qs  + BQ * HD_;           // [HD][BKT+1]       4160 (d-major)
    float* Vs    = Kst + HD_ * (BKT + 1);    // [BKT][HD]         4096
    float* Ss    = Vs  + BKT * HD_;          // [BQ][BKT+1]       4160
    float* m_s   = Ss  + BQ * (BKT + 1);     // [BQ]
    float* l_s   = m_s + BQ;                 // [BQ]
    float* cor_s = l_s + BQ;                 // [BQ]
    __shared__ int mask_s[BKT];

    const int b  = blockIdx.z;
    const int h  = blockIdx.y;
    const int qt = blockIdx.x;
    const int tid = threadIdx.x;
    const int ty = tid >> 4, tx = tid & 15;
    const int rbase = ty * 4, cbase = tx * 4;
    const float scale = 0.125f;   // 1/sqrt(64)

    // Load Q tile (rows qt*64.., head slice h*64..)
    const float* Qbase = Q + ((size_t)b * S_ + (size_t)qt * BQ) * D_ + h * HD_;
    for (int idx = tid; idx < BQ * HD_; idx += 256) {
        int r = idx >> 6, d = idx & 63;
        Qs[r * HD_ + d] = Qbase[(size_t)r * D_ + d];
    }
    if (tid < BQ) { m_s[tid] = -1e30f; l_s[tid] = 0.0f; }

    float acc[4][4];
#pragma unroll
    for (int i = 0; i < 4; ++i)
#pragma unroll
        for (int j = 0; j < 4; ++j) acc[i][j] = 0.0f;

    for (int kt = 0; kt < S_ / BKT; ++kt) {
        const float* Kbase = K + ((size_t)b * S_ + (size_t)kt * BKT) * D_ + h * HD_;
        const float* Vbase = V + ((size_t)b * S_ + (size_t)kt * BKT) * D_ + h * HD_;

        __syncthreads();   // previous iteration done with Kst/Vs/Ss (also covers Q load / m,l init)
        for (int idx = tid; idx < BKT * HD_; idx += 256) {
            int c = idx >> 6, d = idx & 63;
            Kst[d * (BKT + 1) + c] = Kbase[(size_t)c * D_ + d];
            Vs[c * HD_ + d]        = Vbase[(size_t)c * D_ + d];
        }
        if (tid < BKT) mask_s[tid] = mask[(size_t)b * S_ + (size_t)kt * BKT + tid];
        __syncthreads();

        // S tile = scale * Q K^T
        float s[4][4];
#pragma unroll
        for (int i = 0; i < 4; ++i)
#pragma unroll
            for (int j = 0; j < 4; ++j) s[i][j] = 0.0f;

        for (int d = 0; d < HD_; ++d) {
            float qv[4], kv[4];
#pragma unroll
            for (int i = 0; i < 4; ++i) qv[i] = Qs[(rbase + i) * HD_ + d];
#pragma unroll
            for (int j = 0; j < 4; ++j) kv[j] = Kst[d * (BKT + 1) + cbase + j];
#pragma unroll
            for (int i = 0; i < 4; ++i)
#pragma unroll
                for (int j = 0; j < 4; ++j)
                    s[i][j] = fmaf(qv[i], kv[j], s[i][j]);
        }

#pragma unroll
        for (int i = 0; i < 4; ++i)
#pragma unroll
            for (int j = 0; j < 4; ++j) {
                float val = s[i][j] * scale;
                if (mask_s[cbase + j] == 0) val = -1e9f;
                Ss[(rbase + i) * (BKT + 1) + cbase + j] = val;
            }
        __syncthreads();

        // Online softmax (rows handled by threads 0..63)
        if (tid < BQ) {
            const int r = tid;
            float mOld = m_s[r];
            float mx = mOld;
            for (int c = 0; c < BKT; ++c)
                mx = fmaxf(mx, Ss[r * (BKT + 1) + c]);
            float corr = __expf(mOld - mx);
            float sum = 0.0f;
            for (int c = 0; c < BKT; ++c) {
                float p = __expf(Ss[r * (BKT + 1) + c] - mx);
                Ss[r * (BKT + 1) + c] = p;
                sum += p;
            }
            l_s[r] = l_s[r] * corr + sum;
            m_s[r] = mx;
            cor_s[r] = corr;
        }
        __syncthreads();

        // rescale accumulator, then O += P * V
        float cr[4];
#pragma unroll
        for (int i = 0; i < 4; ++i) cr[i] = cor_s[rbase + i];
#pragma unroll
        for (int i = 0; i < 4; ++i)
#pragma unroll
            for (int j = 0; j < 4; ++j) acc[i][j] *= cr[i];

        for (int c = 0; c < BKT; ++c) {
            float pv[4], vv[4];
#pragma unroll
            for (int i = 0; i < 4; ++i) pv[i] = Ss[(rbase + i) * (BKT + 1) + c];
#pragma unroll
            for (int j = 0; j < 4; ++j) vv[j] = Vs[c * HD_ + cbase + j];
#pragma unroll
            for (int i = 0; i < 4; ++i)
#pragma unroll
                for (int j = 0; j < 4; ++j)
                    acc[i][j] = fmaf(pv[i], vv[j], acc[i][j]);
        }
    }

    __syncthreads();
    float linv[4];
#pragma unroll
    for (int i = 0; i < 4; ++i) linv[i] = 1.0f / l_s[rbase + i];

    float* Obase = O + ((size_t)b * S_ + (size_t)qt * BQ) * D_ + h * HD_;
#pragma unroll
    for (int i = 0; i < 4; ++i)
#pragma unroll
        for (int j = 0; j < 4; ++j)
            Obase[(size_t)(rbase + i) * D_ + cbase + j] = acc[i][j] * linv[i];
}

// ---------------------------- launch ---------------------------------------
extern "C" void kernel_launch(void* const* d_in, const int* in_sizes, int n_in,
                              void* d_out, int out_size) {
    const float* x    = (const float*)d_in[0];
    const int*   mask = (const int*)d_in[1];
    const float* Wq   = (const float*)d_in[2];
    const float* bq   = (const float*)d_in[3];
    const float* Wk   = (const float*)d_in[4];
    const float* bk   = (const float*)d_in[5];
    const float* Wv   = (const float*)d_in[6];
    const float* bv   = (const float*)d_in[7];
    const float* Wo   = (const float*)d_in[8];
    const float* bo   = (const float*)d_in[9];
    float* out = (float*)d_out;

    float *q, *k, *v, *attn;
    cudaGetSymbolAddress((void**)&q,    g_q);
    cudaGetSymbolAddress((void**)&k,    g_k);
    cudaGetSymbolAddress((void**)&v,    g_v);
    cudaGetSymbolAddress((void**)&attn, g_attn);

    dim3 ggrid(D_ / BN, M_ / BM);   // (8, 32)
    sgemm_bias_nt<<<ggrid, 256>>>(x, Wq, bq, q, M_, D_, D_);
    sgemm_bias_nt<<<ggrid, 256>>>(x, Wk, bk, k, M_, D_, D_);
    sgemm_bias_nt<<<ggrid, 256>>>(x, Wv, bv, v, M_, D_, D_);

    const int smem_bytes =
        (BQ * HD_ + HD_ * (BKT + 1) + BKT * HD_ + BQ * (BKT + 1) + 3 * BQ) * (int)sizeof(float);
    static bool attr_set = false;  // host-side config only; idempotent, no device work
    cudaFuncSetAttribute(flash_attn_f32, cudaFuncAttributeMaxDynamicSharedMemorySize, smem_bytes);

    dim3 agrid(S_ / BQ, H_, B_);   // (32, 16, 2)
    flash_attn_f32<<<agrid, 256, smem_bytes>>>(q, k, v, mask, attn);

    sgemm_bias_nt<<<ggrid, 256>>>(attn, Wo, bo, out, M_, D_, D_);
    (void)attr_set; (void)n_in; (void)in_sizes; (void)out_size;
}

// round 2
// speedup vs baseline: 1.0041x; 1.0041x over previous
#include <cuda_runtime.h>
#include <cuda_bf16.h>
#include <math.h>

// Problem constants
#define B_  2
#define S_  2048
#define D_  1024
#define H_  16
#define HD_ 64
#define M_  (B_ * S_)           // 4096 rows for projection GEMMs

// ---------------- scratch (static device globals; no runtime alloc) --------
__device__ float g_q[(size_t)B_ * S_ * D_];
__device__ float g_k[(size_t)B_ * S_ * D_];
__device__ float g_v[(size_t)B_ * S_ * D_];
__device__ float g_attn[(size_t)B_ * S_ * D_];

// ---------------- SGEMM: C[M,N] = A[M,K] * W[N,K]^T + bias[N] --------------
// 128x128 block tile, BK=8, 256 threads, 8x8 per-thread micro tile.
#define BM 128
#define BN 128
#define BKK 8

__global__ __launch_bounds__(256, 2)
void sgemm_bias_nt(const float* __restrict__ A, const float* __restrict__ W,
                   const float* __restrict__ bias, float* __restrict__ C,
                   int M, int N, int K) {
    __shared__ float As[BKK][BM];
    __shared__ float Ws[BKK][BN];

    const int tid = threadIdx.x;
    const int block_row = blockIdx.y * BM;
    const int block_col = blockIdx.x * BN;

    // Global->smem load mapping: 2 threads per row, one float4 each (BK=8)
    const int a_row  = tid >> 1;          // 0..127
    const int a_col4 = (tid & 1) << 2;    // 0 or 4

    const int ty = tid >> 4;              // 0..15
    const int tx = tid & 15;              // 0..15
    const int r0 = ty * 8;
    const int c0 = tx * 8;

    float acc[8][8];
#pragma unroll
    for (int i = 0; i < 8; ++i)
#pragma unroll
        for (int j = 0; j < 8; ++j) acc[i][j] = 0.0f;

    const float* Aptr = A + (size_t)(block_row + a_row) * K + a_col4;
    const float* Wptr = W + (size_t)(block_col + a_row) * K + a_col4;

    for (int k0 = 0; k0 < K; k0 += BKK) {
        float4 av = *(const float4*)(Aptr + k0);
        float4 wv = *(const float4*)(Wptr + k0);

        __syncthreads();   // previous iteration done reading smem
        As[a_col4 + 0][a_row] = av.x;
        As[a_col4 + 1][a_row] = av.y;
        As[a_col4 + 2][a_row] = av.z;
        As[a_col4 + 3][a_row] = av.w;
        Ws[a_col4 + 0][a_row] = wv.x;
        Ws[a_col4 + 1][a_row] = wv.y;
        Ws[a_col4 + 2][a_row] = wv.z;
        Ws[a_col4 + 3][a_row] = wv.w;
        __syncthreads();

#pragma unroll
        for (int kk = 0; kk < BKK; ++kk) {
            float a[8], b[8];
            float4 a0 = *(const float4*)&As[kk][r0];
            float4 a1 = *(const float4*)&As[kk][r0 + 4];
            float4 b0 = *(const float4*)&Ws[kk][c0];
            float4 b1 = *(const float4*)&Ws[kk][c0 + 4];
            a[0]=a0.x; a[1]=a0.y; a[2]=a0.z; a[3]=a0.w;
            a[4]=a1.x; a[5]=a1.y; a[6]=a1.z; a[7]=a1.w;
            b[0]=b0.x; b[1]=b0.y; b[2]=b0.z; b[3]=b0.w;
            b[4]=b1.x; b[5]=b1.y; b[6]=b1.z; b[7]=b1.w;
#pragma unroll
            for (int i = 0; i < 8; ++i)
#pragma unroll
                for (int j = 0; j < 8; ++j)
                    acc[i][j] = fmaf(a[i], b[j], acc[i][j]);
        }
    }

    // epilogue + bias
#pragma unroll
    for (int i = 0; i < 8; ++i) {
        float* crow = C + (size_t)(block_row + r0 + i) * N + block_col + c0;
#pragma unroll
        for (int j = 0; j < 8; ++j) {
            crow[j] = acc[i][j] + bias[block_col + c0 + j];
        }
    }
}

// ---------------- flash attention (fp32, online softmax) -------------------
// One CTA: 64 query rows of one (b, h). Streams 64-row K/V tiles.
// 256 threads as 16x16; each thread owns a 4x4 micro tile.
#define BQ 64
#define BKT 64

__global__ __launch_bounds__(256)
void flash_attn_f32(const float* __restrict__ Q, const float* __restrict__ K,
                    const float* __restrict__ V, const int* __restrict__ mask,
                    float* __restrict__ O) {
    extern __shared__ float sm[];
    float* Qs    = sm;                       // [BQ][HD]          4096
    float* Kst   = Qs  + BQ * HD_;           // [HD][BKT+1]       4160 (d-major)
    float* Vs    = Kst + HD_ * (BKT + 1);    // [BKT][HD]         4096
    float* Ss    = Vs  + BKT * HD_;          // [BQ][BKT+1]       4160
    float* m_s   = Ss  + BQ * (BKT + 1);     // [BQ]
    float* l_s   = m_s + BQ;                 // [BQ]
    float* cor_s = l_s + BQ;                 // [BQ]
    __shared__ int mask_s[BKT];

    const int b  = blockIdx.z;
    const int h  = blockIdx.y;
    const int qt = blockIdx.x;
    const int tid = threadIdx.x;
    const int ty = tid >> 4, tx = tid & 15;
    const int rbase = ty * 4, cbase = tx * 4;
    const float scale = 0.125f;   // 1/sqrt(64)

    // Load Q tile (rows qt*64.., head slice h*64..)
    const float* Qbase = Q + ((size_t)b * S_ + (size_t)qt * BQ) * D_ + h * HD_;
    for (int idx = tid; idx < BQ * HD_; idx += 256) {
        int r = idx >> 6, d = idx & 63;
        Qs[r * HD_ + d] = Qbase[(size_t)r * D_ + d];
    }
    if (tid < BQ) { m_s[tid] = -1e30f; l_s[tid] = 0.0f; }

    float acc[4][4];
#pragma unroll
    for (int i = 0; i < 4; ++i)
#pragma unroll
        for (int j = 0; j < 4; ++j) acc[i][j] = 0.0f;

    for (int kt = 0; kt < S_ / BKT; ++kt) {
        const float* Kbase = K + ((size_t)b * S_ + (size_t)kt * BKT) * D_ + h * HD_;
        const float* Vbase = V + ((size_t)b * S_ + (size_t)kt * BKT) * D_ + h * HD_;

        __syncthreads();   // previous iteration done with Kst/Vs/Ss (also covers Q load / m,l init)
        for (int idx = tid; idx < BKT * HD_; idx += 256) {
            int c = idx >> 6, d = idx & 63;
            Kst[d * (BKT + 1) + c] = Kbase[(size_t)c * D_ + d];
            Vs[c * HD_ + d]        = Vbase[(size_t)c * D_ + d];
        }
        if (tid < BKT) mask_s[tid] = mask[(size_t)b * S_ + (size_t)kt * BKT + tid];
        __syncthreads();

        // S tile = scale * Q K^T
        float s[4][4];
#pragma unroll
        for (int i = 0; i < 4; ++i)
#pragma unroll
            for (int j = 0; j < 4; ++j) s[i][j] = 0.0f;

        for (int d = 0; d < HD_; ++d) {
            float qv[4], kv[4];
#pragma unroll
            for (int i = 0; i < 4; ++i) qv[i] = Qs[(rbase + i) * HD_ + d];
#pragma unroll
            for (int j = 0; j < 4; ++j) kv[j] = Kst[d * (BKT + 1) + cbase + j];
#pragma unroll
            for (int i = 0; i < 4; ++i)
#pragma unroll
                for (int j = 0; j < 4; ++j)
                    s[i][j] = fmaf(qv[i], kv[j], s[i][j]);
        }

#pragma unroll
        for (int i = 0; i < 4; ++i)
#pragma unroll
            for (int j = 0; j < 4; ++j) {
                float val = s[i][j] * scale;
                if (mask_s[cbase + j] == 0) val = -1e9f;
                Ss[(rbase + i) * (BKT + 1) + cbase + j] = val;
            }
        __syncthreads();

        // Online softmax (rows handled by threads 0..63)
        if (tid < BQ) {
            const int r = tid;
            float mOld = m_s[r];
            float mx = mOld;
            for (int c = 0; c < BKT; ++c)
                mx = fmaxf(mx, Ss[r * (BKT + 1) + c]);
            float corr = __expf(mOld - mx);
            float sum = 0.0f;
            for (int c = 0; c < BKT; ++c) {
                float p = __expf(Ss[r * (BKT + 1) + c] - mx);
                Ss[r * (BKT + 1) + c] = p;
                sum += p;
            }
            l_s[r] = l_s[r] * corr + sum;
            m_s[r] = mx;
            cor_s[r] = corr;
        }
        __syncthreads();

        // rescale accumulator, then O += P * V
        float cr[4];
#pragma unroll
        for (int i = 0; i < 4; ++i) cr[i] = cor_s[rbase + i];
#pragma unroll
        for (int i = 0; i < 4; ++i)
#pragma unroll
            for (int j = 0; j < 4; ++j) acc[i][j] *= cr[i];

        for (int c = 0; c < BKT; ++c) {
            float pv[4], vv[4];
#pragma unroll
            for (int i = 0; i < 4; ++i) pv[i] = Ss[(rbase + i) * (BKT + 1) + c];
#pragma unroll
            for (int j = 0; j < 4; ++j) vv[j] = Vs[c * HD_ + cbase + j];
#pragma unroll
            for (int i = 0; i < 4; ++i)
#pragma unroll
                for (int j = 0; j < 4; ++j)
                    acc[i][j] = fmaf(pv[i], vv[j], acc[i][j]);
        }
    }

    __syncthreads();
    float linv[4];
#pragma unroll
    for (int i = 0; i < 4; ++i) linv[i] = 1.0f / l_s[rbase + i];

    float* Obase = O + ((size_t)b * S_ + (size_t)qt * BQ) * D_ + h * HD_;
#pragma unroll
    for (int i = 0; i < 4; ++i)
#pragma unroll
        for (int j = 0; j < 4; ++j)
            Obase[(size_t)(rbase + i) * D_ + cbase + j] = acc[i][j] * linv[i];
}

// ---------------------------- launch ---------------------------------------
extern "C" void kernel_launch(void* const* d_in, const int* in_sizes, int n_in,
                              void* d_out, int out_size) {
    const float* x    = (const float*)d_in[0];
    const int*   mask = (const int*)d_in[1];
    const float* Wq   = (const float*)d_in[2];
    const float* bq   = (const float*)d_in[3];
    const float* Wk   = (const float*)d_in[4];
    const float* bk   = (const float*)d_in[5];
    const float* Wv   = (const float*)d_in[6];
    const float* bv   = (const float*)d_in[7];
    const float* Wo   = (const float*)d_in[8];
    const float* bo   = (const float*)d_in[9];
    float* out = (float*)d_out;

    float *q, *k, *v, *attn;
    cudaGetSymbolAddress((void**)&q,    g_q);
    cudaGetSymbolAddress((void**)&k,    g_k);
    cudaGetSymbolAddress((void**)&v,    g_v);
    cudaGetSymbolAddress((void**)&attn, g_attn);

    dim3 ggrid(D_ / BN, M_ / BM);   // (8, 32)
    sgemm_bias_nt<<<ggrid, 256>>>(x, Wq, bq, q, M_, D_, D_);
    sgemm_bias_nt<<<ggrid, 256>>>(x, Wk, bk, k, M_, D_, D_);
    sgemm_bias_nt<<<ggrid, 256>>>(x, Wv, bv, v, M_, D_, D_);

    const int smem_bytes =
        (BQ * HD_ + HD_ * (BKT + 1) + BKT * HD_ + BQ * (BKT + 1) + 3 * BQ) * (int)sizeof(float);
    static bool attr_set = false;  // host-side config only; idempotent, no device work
    cudaFuncSetAttribute(flash_attn_f32, cudaFuncAttributeMaxDynamicSharedMemorySize, smem_bytes);

    dim3 agrid(S_ / BQ, H_, B_);   // (32, 16, 2)
    flash_attn_f32<<<agrid, 256, smem_bytes>>>(q, k, v, mask, attn);

    sgemm_bias_nt<<<ggrid, 256>>>(attn, Wo, bo, out, M_, D_, D_);
    (void)attr_set; (void)n_in; (void)in_sizes; (void)out_size;
}

// round 4
// speedup vs baseline: 6.4988x; 6.4721x over previous
#include <cuda_runtime.h>
#include <cuda_fp16.h>
#include <cstdint>

#define B_  2
#define S_  2048
#define D_  1024
#define H_  16
#define HD_ 64
#define M_  (B_ * S_)

// ---------------- scratch (static device globals) ---------------------------
__device__ __align__(16) __half g_xh[(size_t)M_ * D_];
__device__ __align__(16) __half g_wh[4][(size_t)D_ * D_];
__device__ __align__(16) __half g_qh[(size_t)M_ * D_];
__device__ __align__(16) __half g_kh[(size_t)M_ * D_];
__device__ __align__(16) __half g_vh[(size_t)M_ * D_];
__device__ __align__(16) __half g_ah[(size_t)M_ * D_];

// ---------------- PTX helpers (all plain compute_103 features) --------------
__device__ __forceinline__ uint32_t smem_u32(const void* p) {
    uint32_t a;
    asm("{ .reg .u64 t; cvta.to.shared.u64 t, %1; cvt.u32.u64 %0, t; }" : "=r"(a) : "l"(p));
    return a;
}
__device__ __forceinline__ void ldsm4(uint32_t& r0, uint32_t& r1, uint32_t& r2, uint32_t& r3,
                                      uint32_t a) {
    asm volatile("ldmatrix.sync.aligned.m8n8.x4.shared.b16 {%0,%1,%2,%3}, [%4];"
                 : "=r"(r0), "=r"(r1), "=r"(r2), "=r"(r3) : "r"(a));
}
__device__ __forceinline__ void ldsm4t(uint32_t& r0, uint32_t& r1, uint32_t& r2, uint32_t& r3,
                                       uint32_t a) {
    asm volatile("ldmatrix.sync.aligned.m8n8.x4.trans.shared.b16 {%0,%1,%2,%3}, [%4];"
                 : "=r"(r0), "=r"(r1), "=r"(r2), "=r"(r3) : "r"(a));
}
__device__ __forceinline__ void mma16816(float* c, const uint32_t* a, const uint32_t* b) {
    asm volatile(
        "mma.sync.aligned.m16n8k16.row.col.f32.f16.f16.f32 "
        "{%0,%1,%2,%3}, {%4,%5,%6,%7}, {%8,%9}, {%0,%1,%2,%3};"
        : "+f"(c[0]), "+f"(c[1]), "+f"(c[2]), "+f"(c[3])
        : "r"(a[0]), "r"(a[1]), "r"(a[2]), "r"(a[3]), "r"(b[0]), "r"(b[1]));
}
#define CPA(s, g) asm volatile("cp.async.cg.shared.global [%0], [%1], 16;" :: "r"(s), "l"(g))
#define CPC()     asm volatile("cp.async.commit_group;" ::: "memory")
#define CPW1()    asm volatile("cp.async.wait_group 1;" ::: "memory")

__device__ __forceinline__ uint32_t packh2(float a, float b) {
    __half2 h = __floats2half2_rn(a, b);
    return *reinterpret_cast<uint32_t*>(&h);
}

// ---------------- fp32 -> fp16 convert --------------------------------------
__global__ __launch_bounds__(256)
void cvt_f32_f16(const float* __restrict__ in, __half* __restrict__ out, int n) {
    int i = (blockIdx.x * 256 + threadIdx.x) * 8;
    if (i >= n) return;
    float4 v0 = *(const float4*)(in + i);
    float4 v1 = *(const float4*)(in + i + 4);
    __half2 h[4] = { __floats2half2_rn(v0.x, v0.y), __floats2half2_rn(v0.z, v0.w),
                     __floats2half2_rn(v1.x, v1.y), __floats2half2_rn(v1.z, v1.w) };
    *(uint4*)(out + i) = *(uint4*)h;
}

// ---------------- fp16 HMMA GEMM: C = A * W^T + bias ------------------------
// A[M,1024] fp16, W[1024,1024] fp16 (both K-contiguous). CTA 128x128, BK=32.
#define GBM 128
#define GBK 32
#define GSTR 40   // halves; 80B row stride -> conflict-free LDSM

template<bool F16OUT>
__global__ __launch_bounds__(256)
void gemm_f16(const __half* __restrict__ A, const __half* __restrict__ Wt,
              const float* __restrict__ bias, void* __restrict__ Cout) {
    __shared__ __align__(16) __half As[2][GBM * GSTR];
    __shared__ __align__(16) __half Ws[2][GBM * GSTR];

    const int tid = threadIdx.x;
    const int wid = tid >> 5, lane = tid & 31;
    const int bm = blockIdx.y * GBM, bn = blockIdx.x * GBM;
    const int wm = (wid & 3) * 32, wn = (wid >> 2) * 64;

    float acc[2][8][4];
#pragma unroll
    for (int mt = 0; mt < 2; ++mt)
#pragma unroll
        for (int nt = 0; nt < 8; ++nt)
#pragma unroll
            for (int j = 0; j < 4; ++j) acc[mt][nt][j] = 0.0f;

    const int lrow = tid >> 2, lc = (tid & 3) * 8;        // 16B chunk per thread
    const __half* gA = A  + (size_t)(bm + lrow) * D_ + lc;
    const __half* gW = Wt + (size_t)(bn + lrow) * D_ + lc;
    const __half* gA2 = A  + (size_t)(bm + lrow + 64) * D_ + lc;
    const __half* gW2 = Wt + (size_t)(bn + lrow + 64) * D_ + lc;

#define GLOAD(kc, buf) do {                                                    \
    uint32_t s;                                                                \
    s = smem_u32(&As[buf][lrow * GSTR + lc]);        CPA(s, gA  + (kc) * GBK); \
    s = smem_u32(&As[buf][(lrow + 64) * GSTR + lc]); CPA(s, gA2 + (kc) * GBK); \
    s = smem_u32(&Ws[buf][lrow * GSTR + lc]);        CPA(s, gW  + (kc) * GBK); \
    s = smem_u32(&Ws[buf][(lrow + 64) * GSTR + lc]); CPA(s, gW2 + (kc) * GBK); \
} while (0)

    GLOAD(0, 0);
    CPC();
    int buf = 0;
    for (int kc = 0; kc < D_ / GBK; ++kc) {
        if (kc + 1 < D_ / GBK) GLOAD(kc + 1, buf ^ 1);
        CPC();
        CPW1();
        __syncthreads();
#pragma unroll
        for (int ks = 0; ks < 2; ++ks) {
            uint32_t af[2][4];
#pragma unroll
            for (int mt = 0; mt < 2; ++mt) {
                int row = wm + mt * 16 + (lane & 15);
                int col = ks * 16 + (lane >> 4) * 8;
                ldsm4(af[mt][0], af[mt][1], af[mt][2], af[mt][3],
                      smem_u32(&As[buf][row * GSTR + col]));
            }
            uint32_t bf[8][2];
#pragma unroll
            for (int np = 0; np < 4; ++np) {
                int q = lane >> 3;
                int row = wn + np * 16 + (q >> 1) * 8 + (lane & 7);
                int col = ks * 16 + (q & 1) * 8;
                uint32_t r0, r1, r2, r3;
                ldsm4(r0, r1, r2, r3, smem_u32(&Ws[buf][row * GSTR + col]));
                bf[np * 2][0] = r0; bf[np * 2][1] = r1;
                bf[np * 2 + 1][0] = r2; bf[np * 2 + 1][1] = r3;
            }
#pragma unroll
            for (int mt = 0; mt < 2; ++mt)
#pragma unroll
                for (int nt = 0; nt < 8; ++nt)
                    mma16816(acc[mt][nt], af[mt], bf[nt]);
        }
        __syncthreads();
        buf ^= 1;
    }
#undef GLOAD

#pragma unroll
    for (int mt = 0; mt < 2; ++mt) {
        int row = bm + wm + mt * 16 + (lane >> 2);
#pragma unroll
        for (int nt = 0; nt < 8; ++nt) {
            int col = bn + wn + nt * 8 + (lane & 3) * 2;
            float b0 = bias[col], b1 = bias[col + 1];
            float v0 = acc[mt][nt][0] + b0, v1 = acc[mt][nt][1] + b1;
            float v2 = acc[mt][nt][2] + b0, v3 = acc[mt][nt][3] + b1;
            if (F16OUT) {
                __half* base = (__half*)Cout;
                *(__half2*)(base + (size_t)row * D_ + col)       = __floats2half2_rn(v0, v1);
                *(__half2*)(base + (size_t)(row + 8) * D_ + col) = __floats2half2_rn(v2, v3);
            } else {
                float* base = (float*)Cout;
                *(float2*)(base + (size_t)row * D_ + col)       = make_float2(v0, v1);
                *(float2*)(base + (size_t)(row + 8) * D_ + col) = make_float2(v2, v3);
            }
        }
    }
}

// ---------------- flash attention, fp16 HMMA --------------------------------
// CTA = 64 q-rows of one (b,h); 4 warps x 16 rows. K/V tiles of 64, cp.async 2-buf.
#define AQ 64
#define AK 64
#define ASTR 72   // halves; 144B stride -> conflict-free LDSM

__global__ __launch_bounds__(128)
void flash_f16(const __half* __restrict__ Q, const __half* __restrict__ K,
               const __half* __restrict__ V, const int* __restrict__ mask,
               __half* __restrict__ O) {
    __shared__ __align__(16) __half Qs[AQ * ASTR];
    __shared__ __align__(16) __half Ks[2][AK * ASTR];
    __shared__ __align__(16) __half Vs[2][AK * ASTR];
    __shared__ __align__(16) int    msk[2][AK];

    const int b = blockIdx.z, h = blockIdx.y, qt = blockIdx.x;
    const int tid = threadIdx.x, wid = tid >> 5, lane = tid & 31;

    const __half* Qg = Q + (size_t)(b * S_ + qt * AQ) * D_ + h * HD_;
    const __half* Kg = K + (size_t)(b * S_) * D_ + h * HD_;
    const __half* Vg = V + (size_t)(b * S_) * D_ + h * HD_;
    const int* mg = mask + b * S_;

    const int lr = tid >> 1, lc8 = (tid & 1) * 8;   // 2 chunks/row covers 64 rows per 128 thr... 
    // (64 rows x 128B = 512 chunks; 128 threads x 4)
#define KVLOAD(kt, buf) do {                                                       \
    _Pragma("unroll")                                                              \
    for (int i = 0; i < 4; ++i) {                                                  \
        int idx = tid + i * 128; int r = idx >> 3, c = (idx & 7) * 8;              \
        CPA(smem_u32(&Ks[buf][r * ASTR + c]), Kg + (size_t)((kt) * AK + r) * D_ + c); \
        CPA(smem_u32(&Vs[buf][r * ASTR + c]), Vg + (size_t)((kt) * AK + r) * D_ + c); \
    }                                                                              \
    if (tid < 16) CPA(smem_u32(&msk[buf][tid * 4]), mg + (kt) * AK + tid * 4);     \
} while (0)

    // prologue: Q + tile0
#pragma unroll
    for (int i = 0; i < 4; ++i) {
        int idx = tid + i * 128; int r = idx >> 3, c = (idx & 7) * 8;
        CPA(smem_u32(&Qs[r * ASTR + c]), Qg + (size_t)r * D_ + c);
    }
    KVLOAD(0, 0);
    CPC();

    float m0 = -1e30f, m1 = -1e30f, l0 = 0.0f, l1 = 0.0f;
    float oacc[8][4];
#pragma unroll
    for (int nt = 0; nt < 8; ++nt)
#pragma unroll
        for (int j = 0; j < 4; ++j) oacc[nt][j] = 0.0f;
    uint32_t qf[4][4];

    int buf = 0;
    for (int kt = 0; kt < S_ / AK; ++kt) {
        if (kt + 1 < S_ / AK) KVLOAD(kt + 1, buf ^ 1);
        CPC();
        CPW1();
        __syncthreads();
        if (kt == 0) {
#pragma unroll
            for (int ks = 0; ks < 4; ++ks) {
                int row = wid * 16 + (lane & 15);
                int col = ks * 16 + (lane >> 4) * 8;
                ldsm4(qf[ks][0], qf[ks][1], qf[ks][2], qf[ks][3],
                      smem_u32(&Qs[row * ASTR + col]));
            }
        }

        // ---- S = Q K^T ----
        float sacc[8][4];
#pragma unroll
        for (int nt = 0; nt < 8; ++nt)
#pragma unroll
            for (int j = 0; j < 4; ++j) sacc[nt][j] = 0.0f;
#pragma unroll
        for (int ks = 0; ks < 4; ++ks) {
            uint32_t bfr[8][2];
#pragma unroll
            for (int np = 0; np < 4; ++np) {
                int q = lane >> 3;
                int row = np * 16 + (q >> 1) * 8 + (lane & 7);
                int col = ks * 16 + (q & 1) * 8;
                uint32_t r0, r1, r2, r3;
                ldsm4(r0, r1, r2, r3, smem_u32(&Ks[buf][row * ASTR + col]));
                bfr[np * 2][0] = r0; bfr[np * 2][1] = r1;
                bfr[np * 2 + 1][0] = r2; bfr[np * 2 + 1][1] = r3;
            }
#pragma unroll
            for (int nt = 0; nt < 8; ++nt) mma16816(sacc[nt], qf[ks], bfr[nt]);
        }

        // ---- scale + mask + online softmax ----
        const float scale = 0.125f;
        const int cc = (lane & 3) * 2;
#pragma unroll
        for (int nt = 0; nt < 8; ++nt) {
            int col = nt * 8 + cc;
            float ma = msk[buf][col]     ? 0.0f : -1e9f;
            float mb = msk[buf][col + 1] ? 0.0f : -1e9f;
            sacc[nt][0] = sacc[nt][0] * scale + ma;
            sacc[nt][1] = sacc[nt][1] * scale + mb;
            sacc[nt][2] = sacc[nt][2] * scale + ma;
            sacc[nt][3] = sacc[nt][3] * scale + mb;
        }
        float rx0 = -1e30f, rx1 = -1e30f;
#pragma unroll
        for (int nt = 0; nt < 8; ++nt) {
            rx0 = fmaxf(rx0, fmaxf(sacc[nt][0], sacc[nt][1]));
            rx1 = fmaxf(rx1, fmaxf(sacc[nt][2], sacc[nt][3]));
        }
        rx0 = fmaxf(rx0, __shfl_xor_sync(0xffffffffu, rx0, 1));
        rx0 = fmaxf(rx0, __shfl_xor_sync(0xffffffffu, rx0, 2));
        rx1 = fmaxf(rx1, __shfl_xor_sync(0xffffffffu, rx1, 1));
        rx1 = fmaxf(rx1, __shfl_xor_sync(0xffffffffu, rx1, 2));
        float mn0 = fmaxf(m0, rx0), mn1 = fmaxf(m1, rx1);
        float cor0 = __expf(m0 - mn0), cor1 = __expf(m1 - mn1);
        m0 = mn0; m1 = mn1;
        float rs0 = 0.0f, rs1 = 0.0f;
#pragma unroll
        for (int nt = 0; nt < 8; ++nt) {
            sacc[nt][0] = __expf(sacc[nt][0] - mn0);
            sacc[nt][1] = __expf(sacc[nt][1] - mn0);
            sacc[nt][2] = __expf(sacc[nt][2] - mn1);
            sacc[nt][3] = __expf(sacc[nt][3] - mn1);
            rs0 += sacc[nt][0] + sacc[nt][1];
            rs1 += sacc[nt][2] + sacc[nt][3];
        }
        rs0 += __shfl_xor_sync(0xffffffffu, rs0, 1);
        rs0 += __shfl_xor_sync(0xffffffffu, rs0, 2);
        rs1 += __shfl_xor_sync(0xffffffffu, rs1, 1);
        rs1 += __shfl_xor_sync(0xffffffffu, rs1, 2);
        l0 = l0 * cor0 + rs0;
        l1 = l1 * cor1 + rs1;
#pragma unroll
        for (int nt = 0; nt < 8; ++nt) {
            oacc[nt][0] *= cor0; oacc[nt][1] *= cor0;
            oacc[nt][2] *= cor1; oacc[nt][3] *= cor1;
        }

        // ---- O += P V  (P regs reused as A-fragments) ----
#pragma unroll
        for (int ks = 0; ks < 4; ++ks) {
            uint32_t pa[4];
            pa[0] = packh2(sacc[2 * ks][0],     sacc[2 * ks][1]);
            pa[1] = packh2(sacc[2 * ks][2],     sacc[2 * ks][3]);
            pa[2] = packh2(sacc[2 * ks + 1][0], sacc[2 * ks + 1][1]);
            pa[3] = packh2(sacc[2 * ks + 1][2], sacc[2 * ks + 1][3]);
            uint32_t bfr[8][2];
#pragma unroll
            for (int np = 0; np < 4; ++np) {
                int q = lane >> 3;
                int row = ks * 16 + (q & 1) * 8 + (lane & 7);   // kt dim
                int col = np * 16 + (q >> 1) * 8;               // d dim (halves)
                uint32_t r0, r1, r2, r3;
                ldsm4t(r0, r1, r2, r3, smem_u32(&Vs[buf][row * ASTR + col]));
                bfr[np * 2][0] = r0; bfr[np * 2][1] = r1;
                bfr[np * 2 + 1][0] = r2; bfr[np * 2 + 1][1] = r3;
            }
#pragma unroll
            for (int nt = 0; nt < 8; ++nt) mma16816(oacc[nt], pa, bfr[nt]);
        }
        __syncthreads();
        buf ^= 1;
    }
#undef KVLOAD

    float li0 = 1.0f / l0, li1 = 1.0f / l1;
    __half* Og = O + (size_t)(b * S_ + qt * AQ + wid * 16) * D_ + h * HD_;
    int r0 = lane >> 2;
#pragma unroll
    for (int nt = 0; nt < 8; ++nt) {
        int col = nt * 8 + (lane & 3) * 2;
        *(__half2*)(Og + (size_t)r0 * D_ + col) =
            __floats2half2_rn(oacc[nt][0] * li0, oacc[nt][1] * li0);
        *(__half2*)(Og + (size_t)(r0 + 8) * D_ + col) =
            __floats2half2_rn(oacc[nt][2] * li1, oacc[nt][3] * li1);
    }
    (void)lr; (void)lc8;
}

// ---------------------------- launch ---------------------------------------
extern "C" void kernel_launch(void* const* d_in, const int* in_sizes, int n_in,
                              void* d_out, int out_size) {
    const float* x    = (const float*)d_in[0];
    const int*   mask = (const int*)d_in[1];
    const float* Wq   = (const float*)d_in[2];
    const float* bq   = (const float*)d_in[3];
    const float* Wk   = (const float*)d_in[4];
    const float* bk   = (const float*)d_in[5];
    const float* Wv   = (const float*)d_in[6];
    const float* bv   = (const float*)d_in[7];
    const float* Wo   = (const float*)d_in[8];
    const float* bo   = (const float*)d_in[9];
    float* out = (float*)d_out;

    __half *xh, *wh, *qh, *kh, *vh, *ah;
    cudaGetSymbolAddress((void**)&xh, g_xh);
    cudaGetSymbolAddress((void**)&wh, g_wh);
    cudaGetSymbolAddress((void**)&qh, g_qh);
    cudaGetSymbolAddress((void**)&kh, g_kh);
    cudaGetSymbolAddress((void**)&vh, g_vh);
    cudaGetSymbolAddress((void**)&ah, g_ah);
    const size_t WSZ = (size_t)D_ * D_;

    cvt_f32_f16<<<(M_ * D_) / 2048, 256>>>(x, xh, M_ * D_);
    cvt_f32_f16<<<(D_ * D_) / 2048, 256>>>(Wq, wh + 0 * WSZ, D_ * D_);
    cvt_f32_f16<<<(D_ * D_) / 2048, 256>>>(Wk, wh + 1 * WSZ, D_ * D_);
    cvt_f32_f16<<<(D_ * D_) / 2048, 256>>>(Wv, wh + 2 * WSZ, D_ * D_);
    cvt_f32_f16<<<(D_ * D_) / 2048, 256>>>(Wo, wh + 3 * WSZ, D_ * D_);

    dim3 ggrid(D_ / 128, M_ / 128);   // (8, 32)
    gemm_f16<true><<<ggrid, 256>>>(xh, wh + 0 * WSZ, bq, qh);
    gemm_f16<true><<<ggrid, 256>>>(xh, wh + 1 * WSZ, bk, kh);
    gemm_f16<true><<<ggrid, 256>>>(xh, wh + 2 * WSZ, bv, vh);

    dim3 agrid(S_ / AQ, H_, B_);      // (32, 16, 2)
    flash_f16<<<agrid, 128>>>(qh, kh, vh, mask, ah);

    gemm_f16<false><<<ggrid, 256>>>(ah, wh + 3 * WSZ, bo, out);
    (void)n_in; (void)in_sizes; (void)out_size;
}

// round 5
// speedup vs baseline: 6.8066x; 1.0474x over previous
#include <cuda_runtime.h>
#include <cuda_fp16.h>
#include <cstdint>

#define B_  2
#define S_  2048
#define D_  1024
#define H_  16
#define HD_ 64
#define M_  (B_ * S_)

// ---------------- scratch (static device globals) ---------------------------
__device__ __align__(16) __half g_xh[(size_t)M_ * D_];
__device__ __align__(16) __half g_wh[4][(size_t)D_ * D_];
__device__ __align__(16) __half g_qh[(size_t)M_ * D_];
__device__ __align__(16) __half g_kh[(size_t)M_ * D_];
__device__ __align__(16) __half g_vh[(size_t)M_ * D_];
__device__ __align__(16) __half g_ah[(size_t)M_ * D_];

// ---------------- PTX helpers (plain compute_103 features only) -------------
__device__ __forceinline__ uint32_t smem_u32(const void* p) {
    uint32_t a;
    asm("{ .reg .u64 t; cvta.to.shared.u64 t, %1; cvt.u32.u64 %0, t; }" : "=r"(a) : "l"(p));
    return a;
}
__device__ __forceinline__ void ldsm4(uint32_t& r0, uint32_t& r1, uint32_t& r2, uint32_t& r3,
                                      uint32_t a) {
    asm volatile("ldmatrix.sync.aligned.m8n8.x4.shared.b16 {%0,%1,%2,%3}, [%4];"
                 : "=r"(r0), "=r"(r1), "=r"(r2), "=r"(r3) : "r"(a));
}
__device__ __forceinline__ void ldsm4t(uint32_t& r0, uint32_t& r1, uint32_t& r2, uint32_t& r3,
                                       uint32_t a) {
    asm volatile("ldmatrix.sync.aligned.m8n8.x4.trans.shared.b16 {%0,%1,%2,%3}, [%4];"
                 : "=r"(r0), "=r"(r1), "=r"(r2), "=r"(r3) : "r"(a));
}
__device__ __forceinline__ void mma16816(float* c, const uint32_t* a, const uint32_t* b) {
    asm volatile(
        "mma.sync.aligned.m16n8k16.row.col.f32.f16.f16.f32 "
        "{%0,%1,%2,%3}, {%4,%5,%6,%7}, {%8,%9}, {%0,%1,%2,%3};"
        : "+f"(c[0]), "+f"(c[1]), "+f"(c[2]), "+f"(c[3])
        : "r"(a[0]), "r"(a[1]), "r"(a[2]), "r"(a[3]), "r"(b[0]), "r"(b[1]));
}
#define CPA(s, g) asm volatile("cp.async.cg.shared.global [%0], [%1], 16;" :: "r"(s), "l"(g))
#define CPC()     asm volatile("cp.async.commit_group;" ::: "memory")
#define CPW1()    asm volatile("cp.async.wait_group 1;" ::: "memory")

__device__ __forceinline__ uint32_t packh2(float a, float b) {
    __half2 h = __floats2half2_rn(a, b);
    return *reinterpret_cast<uint32_t*>(&h);
}

// ---------------- fp32 -> fp16 convert --------------------------------------
__global__ __launch_bounds__(256)
void cvt_f32_f16(const float* __restrict__ in, __half* __restrict__ out, int n) {
    int i = (blockIdx.x * 256 + threadIdx.x) * 8;
    if (i >= n) return;
    float4 v0 = *(const float4*)(in + i);
    float4 v1 = *(const float4*)(in + i + 4);
    __half2 h[4] = { __floats2half2_rn(v0.x, v0.y), __floats2half2_rn(v0.z, v0.w),
                     __floats2half2_rn(v1.x, v1.y), __floats2half2_rn(v1.z, v1.w) };
    *(uint4*)(out + i) = *(uint4*)h;
}

// ---------------- fp16 HMMA GEMM: C = A * W^T + bias ------------------------
// CTA 128x128, BK=64, 2-stage cp.async, 8 warps (32x64 each).
#define GBM 128
#define GBK 64
#define GSTR 72   // halves; 144B stride -> conflict-free LDSM (16B phase)
#define GBUF (GBM * GSTR)
#define GSMEM_BYTES (4 * GBUF * 2)   // As[2] + Ws[2]

template<bool F16OUT>
__global__ __launch_bounds__(256)
void gemm_f16(const __half* __restrict__ A, const __half* __restrict__ Wt,
              const float* __restrict__ bias, void* __restrict__ Cout) {
    extern __shared__ __align__(16) __half gsm[];
    __half* As = gsm;              // [2][GBM*GSTR]
    __half* Ws = gsm + 2 * GBUF;   // [2][GBM*GSTR]

    const int tid = threadIdx.x;
    const int wid = tid >> 5, lane = tid & 31;
    const int bm = blockIdx.y * GBM, bn = blockIdx.x * GBM;
    const int wm = (wid & 3) * 32, wn = (wid >> 2) * 64;

    float acc[2][8][4];
#pragma unroll
    for (int mt = 0; mt < 2; ++mt)
#pragma unroll
        for (int nt = 0; nt < 8; ++nt)
#pragma unroll
            for (int j = 0; j < 4; ++j) acc[mt][nt][j] = 0.0f;

#define GLOAD(kc, buf) do {                                                        \
    _Pragma("unroll")                                                              \
    for (int i = 0; i < 4; ++i) {                                                  \
        int idx = tid + i * 256; int r = idx >> 3, c = (idx & 7) * 8;              \
        CPA(smem_u32(&As[(buf) * GBUF + r * GSTR + c]),                            \
            A + (size_t)(bm + r) * D_ + (kc) * GBK + c);                           \
        CPA(smem_u32(&Ws[(buf) * GBUF + r * GSTR + c]),                            \
            Wt + (size_t)(bn + r) * D_ + (kc) * GBK + c);                          \
    }                                                                              \
} while (0)

    GLOAD(0, 0);
    CPC();
    int buf = 0;
    for (int kc = 0; kc < D_ / GBK; ++kc) {
        if (kc + 1 < D_ / GBK) GLOAD(kc + 1, buf ^ 1);
        CPC();
        CPW1();
        __syncthreads();
        const __half* Ab = As + buf * GBUF;
        const __half* Wb = Ws + buf * GBUF;
#pragma unroll
        for (int ks = 0; ks < 4; ++ks) {
            uint32_t af[2][4];
#pragma unroll
            for (int mt = 0; mt < 2; ++mt) {
                int row = wm + mt * 16 + (lane & 15);
                int col = ks * 16 + (lane >> 4) * 8;
                ldsm4(af[mt][0], af[mt][1], af[mt][2], af[mt][3],
                      smem_u32(&Ab[row * GSTR + col]));
            }
            uint32_t bf[8][2];
#pragma unroll
            for (int np = 0; np < 4; ++np) {
                int q = lane >> 3;
                int row = wn + np * 16 + (q >> 1) * 8 + (lane & 7);
                int col = ks * 16 + (q & 1) * 8;
                uint32_t r0, r1, r2, r3;
                ldsm4(r0, r1, r2, r3, smem_u32(&Wb[row * GSTR + col]));
                bf[np * 2][0] = r0; bf[np * 2][1] = r1;
                bf[np * 2 + 1][0] = r2; bf[np * 2 + 1][1] = r3;
            }
#pragma unroll
            for (int mt = 0; mt < 2; ++mt)
#pragma unroll
                for (int nt = 0; nt < 8; ++nt)
                    mma16816(acc[mt][nt], af[mt], bf[nt]);
        }
        __syncthreads();
        buf ^= 1;
    }
#undef GLOAD

#pragma unroll
    for (int mt = 0; mt < 2; ++mt) {
        int row = bm + wm + mt * 16 + (lane >> 2);
#pragma unroll
        for (int nt = 0; nt < 8; ++nt) {
            int col = bn + wn + nt * 8 + (lane & 3) * 2;
            float b0 = bias[col], b1 = bias[col + 1];
            float v0 = acc[mt][nt][0] + b0, v1 = acc[mt][nt][1] + b1;
            float v2 = acc[mt][nt][2] + b0, v3 = acc[mt][nt][3] + b1;
            if (F16OUT) {
                __half* base = (__half*)Cout;
                *(__half2*)(base + (size_t)row * D_ + col)       = __floats2half2_rn(v0, v1);
                *(__half2*)(base + (size_t)(row + 8) * D_ + col) = __floats2half2_rn(v2, v3);
            } else {
                float* base = (float*)Cout;
                *(float2*)(base + (size_t)row * D_ + col)       = make_float2(v0, v1);
                *(float2*)(base + (size_t)(row + 8) * D_ + col) = make_float2(v2, v3);
            }
        }
    }
}

// ---------------- flash attention, fp16 HMMA --------------------------------
// CTA = 128 q-rows of one (b,h); 8 warps x 16 rows. K/V tiles of 64, 2-buf.
#define AQ 128
#define AK 64
#define ASTR 72
#define A_QS   (AQ * ASTR)          // 9216 halves
#define A_KBUF (AK * ASTR)          // 4608 halves
#define ASMEM_BYTES ((A_QS + 4 * A_KBUF) * 2 + 2 * AK * 4)

__global__ __launch_bounds__(256)
void flash_f16(const __half* __restrict__ Q, const __half* __restrict__ K,
               const __half* __restrict__ V, const int* __restrict__ mask,
               __half* __restrict__ O) {
    extern __shared__ __align__(16) __half asm_[];
    __half* Qs = asm_;                    // [AQ][ASTR]
    __half* Ks = asm_ + A_QS;             // [2][AK][ASTR]
    __half* Vs = asm_ + A_QS + 2 * A_KBUF;
    int*    msk = (int*)(asm_ + A_QS + 4 * A_KBUF);  // [2][AK]

    const int b = blockIdx.z, h = blockIdx.y, qt = blockIdx.x;
    const int tid = threadIdx.x, wid = tid >> 5, lane = tid & 31;

    const __half* Qg = Q + (size_t)(b * S_ + qt * AQ) * D_ + h * HD_;
    const __half* Kg = K + (size_t)(b * S_) * D_ + h * HD_;
    const __half* Vg = V + (size_t)(b * S_) * D_ + h * HD_;
    const int* mg = mask + b * S_;

#define KVLOAD(kt, buf) do {                                                          \
    _Pragma("unroll")                                                                 \
    for (int i = 0; i < 2; ++i) {                                                     \
        int idx = tid + i * 256; int r = idx >> 3, c = (idx & 7) * 8;                 \
        CPA(smem_u32(&Ks[(buf) * A_KBUF + r * ASTR + c]),                             \
            Kg + (size_t)((kt) * AK + r) * D_ + c);                                   \
        CPA(smem_u32(&Vs[(buf) * A_KBUF + r * ASTR + c]),                             \
            Vg + (size_t)((kt) * AK + r) * D_ + c);                                   \
    }                                                                                 \
    if (tid < 16) CPA(smem_u32(&msk[(buf) * AK + tid * 4]), mg + (kt) * AK + tid * 4);\
} while (0)

    // prologue: Q (128 rows x 8 chunks = 1024 chunks) + tile0
#pragma unroll
    for (int i = 0; i < 4; ++i) {
        int idx = tid + i * 256; int r = idx >> 3, c = (idx & 7) * 8;
        CPA(smem_u32(&Qs[r * ASTR + c]), Qg + (size_t)r * D_ + c);
    }
    KVLOAD(0, 0);
    CPC();

    float m0 = -1e30f, m1 = -1e30f, l0 = 0.0f, l1 = 0.0f;
    float oacc[8][4];
#pragma unroll
    for (int nt = 0; nt < 8; ++nt)
#pragma unroll
        for (int j = 0; j < 4; ++j) oacc[nt][j] = 0.0f;
    uint32_t qf[4][4];

    int buf = 0;
    for (int kt = 0; kt < S_ / AK; ++kt) {
        if (kt + 1 < S_ / AK) KVLOAD(kt + 1, buf ^ 1);
        CPC();
        CPW1();
        __syncthreads();
        if (kt == 0) {
#pragma unroll
            for (int ks = 0; ks < 4; ++ks) {
                int row = wid * 16 + (lane & 15);
                int col = ks * 16 + (lane >> 4) * 8;
                ldsm4(qf[ks][0], qf[ks][1], qf[ks][2], qf[ks][3],
                      smem_u32(&Qs[row * ASTR + col]));
            }
        }

        // ---- S = Q K^T ----
        float sacc[8][4];
#pragma unroll
        for (int nt = 0; nt < 8; ++nt)
#pragma unroll
            for (int j = 0; j < 4; ++j) sacc[nt][j] = 0.0f;
        const __half* Kb = Ks + buf * A_KBUF;
        const __half* Vb = Vs + buf * A_KBUF;
        const int* mb = msk + buf * AK;
#pragma unroll
        for (int ks = 0; ks < 4; ++ks) {
            uint32_t bfr[8][2];
#pragma unroll
            for (int np = 0; np < 4; ++np) {
                int q = lane >> 3;
                int row = np * 16 + (q >> 1) * 8 + (lane & 7);
                int col = ks * 16 + (q & 1) * 8;
                uint32_t r0, r1, r2, r3;
                ldsm4(r0, r1, r2, r3, smem_u32(&Kb[row * ASTR + col]));
                bfr[np * 2][0] = r0; bfr[np * 2][1] = r1;
                bfr[np * 2 + 1][0] = r2; bfr[np * 2 + 1][1] = r3;
            }
#pragma unroll
            for (int nt = 0; nt < 8; ++nt) mma16816(sacc[nt], qf[ks], bfr[nt]);
        }

        // ---- scale + mask + online softmax ----
        const float scale = 0.125f;
        const int cc = (lane & 3) * 2;
#pragma unroll
        for (int nt = 0; nt < 8; ++nt) {
            int col = nt * 8 + cc;
            float ma = mb[col]     ? 0.0f : -1e9f;
            float mbv = mb[col + 1] ? 0.0f : -1e9f;
            sacc[nt][0] = sacc[nt][0] * scale + ma;
            sacc[nt][1] = sacc[nt][1] * scale + mbv;
            sacc[nt][2] = sacc[nt][2] * scale + ma;
            sacc[nt][3] = sacc[nt][3] * scale + mbv;
        }
        float rx0 = -1e30f, rx1 = -1e30f;
#pragma unroll
        for (int nt = 0; nt < 8; ++nt) {
            rx0 = fmaxf(rx0, fmaxf(sacc[nt][0], sacc[nt][1]));
            rx1 = fmaxf(rx1, fmaxf(sacc[nt][2], sacc[nt][3]));
        }
        rx0 = fmaxf(rx0, __shfl_xor_sync(0xffffffffu, rx0, 1));
        rx0 = fmaxf(rx0, __shfl_xor_sync(0xffffffffu, rx0, 2));
        rx1 = fmaxf(rx1, __shfl_xor_sync(0xffffffffu, rx1, 1));
        rx1 = fmaxf(rx1, __shfl_xor_sync(0xffffffffu, rx1, 2));
        float mn0 = fmaxf(m0, rx0), mn1 = fmaxf(m1, rx1);
        float cor0 = __expf(m0 - mn0), cor1 = __expf(m1 - mn1);
        m0 = mn0; m1 = mn1;
        float rs0 = 0.0f, rs1 = 0.0f;
#pragma unroll
        for (int nt = 0; nt < 8; ++nt) {
            sacc[nt][0] = __expf(sacc[nt][0] - mn0);
            sacc[nt][1] = __expf(sacc[nt][1] - mn0);
            sacc[nt][2] = __expf(sacc[nt][2] - mn1);
            sacc[nt][3] = __expf(sacc[nt][3] - mn1);
            rs0 += sacc[nt][0] + sacc[nt][1];
            rs1 += sacc[nt][2] + sacc[nt][3];
        }
        rs0 += __shfl_xor_sync(0xffffffffu, rs0, 1);
        rs0 += __shfl_xor_sync(0xffffffffu, rs0, 2);
        rs1 += __shfl_xor_sync(0xffffffffu, rs1, 1);
        rs1 += __shfl_xor_sync(0xffffffffu, rs1, 2);
        l0 = l0 * cor0 + rs0;
        l1 = l1 * cor1 + rs1;
#pragma unroll
        for (int nt = 0; nt < 8; ++nt) {
            oacc[nt][0] *= cor0; oacc[nt][1] *= cor0;
            oacc[nt][2] *= cor1; oacc[nt][3] *= cor1;
        }

        // ---- O += P V  (P regs reused as A-fragments) ----
#pragma unroll
        for (int ks = 0; ks < 4; ++ks) {
            uint32_t pa[4];
            pa[0] = packh2(sacc[2 * ks][0],     sacc[2 * ks][1]);
            pa[1] = packh2(sacc[2 * ks][2],     sacc[2 * ks][3]);
            pa[2] = packh2(sacc[2 * ks + 1][0], sacc[2 * ks + 1][1]);
            pa[3] = packh2(sacc[2 * ks + 1][2], sacc[2 * ks + 1][3]);
            uint32_t bfr[8][2];
#pragma unroll
            for (int np = 0; np < 4; ++np) {
                int q = lane >> 3;
                int row = ks * 16 + (q & 1) * 8 + (lane & 7);
                int col = np * 16 + (q >> 1) * 8;
                uint32_t r0, r1, r2, r3;
                ldsm4t(r0, r1, r2, r3, smem_u32(&Vb[row * ASTR + col]));
                bfr[np * 2][0] = r0; bfr[np * 2][1] = r1;
                bfr[np * 2 + 1][0] = r2; bfr[np * 2 + 1][1] = r3;
            }
#pragma unroll
            for (int nt = 0; nt < 8; ++nt) mma16816(oacc[nt], pa, bfr[nt]);
        }
        __syncthreads();
        buf ^= 1;
    }
#undef KVLOAD

    float li0 = 1.0f / l0, li1 = 1.0f / l1;
    __half* Og = O + (size_t)(b * S_ + qt * AQ + wid * 16) * D_ + h * HD_;
    int r0 = lane >> 2;
#pragma unroll
    for (int nt = 0; nt < 8; ++nt) {
        int col = nt * 8 + (lane & 3) * 2;
        *(__half2*)(Og + (size_t)r0 * D_ + col) =
            __floats2half2_rn(oacc[nt][0] * li0, oacc[nt][1] * li0);
        *(__half2*)(Og + (size_t)(r0 + 8) * D_ + col) =
            __floats2half2_rn(oacc[nt][2] * li1, oacc[nt][3] * li1);
    }
}

// ---------------------------- launch ---------------------------------------
extern "C" void kernel_launch(void* const* d_in, const int* in_sizes, int n_in,
                              void* d_out, int out_size) {
    const float* x    = (const float*)d_in[0];
    const int*   mask = (const int*)d_in[1];
    const float* Wq   = (const float*)d_in[2];
    const float* bq   = (const float*)d_in[3];
    const float* Wk   = (const float*)d_in[4];
    const float* bk   = (const float*)d_in[5];
    const float* Wv   = (const float*)d_in[6];
    const float* bv   = (const float*)d_in[7];
    const float* Wo   = (const float*)d_in[8];
    const float* bo   = (const float*)d_in[9];
    float* out = (float*)d_out;

    __half *xh, *wh, *qh, *kh, *vh, *ah;
    cudaGetSymbolAddress((void**)&xh, g_xh);
    cudaGetSymbolAddress((void**)&wh, g_wh);
    cudaGetSymbolAddress((void**)&qh, g_qh);
    cudaGetSymbolAddress((void**)&kh, g_kh);
    cudaGetSymbolAddress((void**)&vh, g_vh);
    cudaGetSymbolAddress((void**)&ah, g_ah);
    const size_t WSZ = (size_t)D_ * D_;

    cudaFuncSetAttribute(gemm_f16<true>,  cudaFuncAttributeMaxDynamicSharedMemorySize, GSMEM_BYTES);
    cudaFuncSetAttribute(gemm_f16<false>, cudaFuncAttributeMaxDynamicSharedMemorySize, GSMEM_BYTES);
    cudaFuncSetAttribute(flash_f16,       cudaFuncAttributeMaxDynamicSharedMemorySize, ASMEM_BYTES);

    cvt_f32_f16<<<(M_ * D_) / 2048, 256>>>(x, xh, M_ * D_);
    cvt_f32_f16<<<(D_ * D_) / 2048, 256>>>(Wq, wh + 0 * WSZ, D_ * D_);
    cvt_f32_f16<<<(D_ * D_) / 2048, 256>>>(Wk, wh + 1 * WSZ, D_ * D_);
    cvt_f32_f16<<<(D_ * D_) / 2048, 256>>>(Wv, wh + 2 * WSZ, D_ * D_);
    cvt_f32_f16<<<(D_ * D_) / 2048, 256>>>(Wo, wh + 3 * WSZ, D_ * D_);

    dim3 ggrid(D_ / 128, M_ / 128);   // (8, 32)
    gemm_f16<true><<<ggrid, 256, GSMEM_BYTES>>>(xh, wh + 0 * WSZ, bq, qh);
    gemm_f16<true><<<ggrid, 256, GSMEM_BYTES>>>(xh, wh + 1 * WSZ, bk, kh);
    gemm_f16<true><<<ggrid, 256, GSMEM_BYTES>>>(xh, wh + 2 * WSZ, bv, vh);

    dim3 agrid(S_ / AQ, H_, B_);      // (16, 16, 2)
    flash_f16<<<agrid, 256, ASMEM_BYTES>>>(qh, kh, vh, mask, ah);

    gemm_f16<false><<<ggrid, 256, GSMEM_BYTES>>>(ah, wh + 3 * WSZ, bo, out);
    (void)n_in; (void)in_sizes; (void)out_size;
}

// round 6
// speedup vs baseline: 7.5674x; 1.1118x over previous
#include <cuda_runtime.h>
#include <cuda_fp16.h>
#include <cstdint>

#define B_  2
#define S_  2048
#define D_  1024
#define H_  16
#define HD_ 64
#define M_  (B_ * S_)
#define NQKV 3072
#define QSCALE 0.18033688f   // (1/sqrt(64)) * log2(e)

// ---------------- scratch (static device globals) ---------------------------
__device__ __align__(16) __half g_xh[(size_t)M_ * D_];
__device__ __align__(16) __half g_wh[(size_t)4 * D_ * D_];   // Wq|Wk|Wv|Wo
__device__ __align__(16) __half g_qkv[(size_t)M_ * NQKV];    // q|k|v interleaved by col
__device__ __align__(16) __half g_ah[(size_t)M_ * D_];
__device__ __align__(16) float  g_bias[NQKV];

// ---------------- PTX helpers ------------------------------------------------
__device__ __forceinline__ uint32_t smem_u32(const void* p) {
    uint32_t a;
    asm("{ .reg .u64 t; cvta.to.shared.u64 t, %1; cvt.u32.u64 %0, t; }" : "=r"(a) : "l"(p));
    return a;
}
__device__ __forceinline__ void ldsm4(uint32_t& r0, uint32_t& r1, uint32_t& r2, uint32_t& r3,
                                      uint32_t a) {
    asm volatile("ldmatrix.sync.aligned.m8n8.x4.shared.b16 {%0,%1,%2,%3}, [%4];"
                 : "=r"(r0), "=r"(r1), "=r"(r2), "=r"(r3) : "r"(a));
}
__device__ __forceinline__ void ldsm4t(uint32_t& r0, uint32_t& r1, uint32_t& r2, uint32_t& r3,
                                       uint32_t a) {
    asm volatile("ldmatrix.sync.aligned.m8n8.x4.trans.shared.b16 {%0,%1,%2,%3}, [%4];"
                 : "=r"(r0), "=r"(r1), "=r"(r2), "=r"(r3) : "r"(a));
}
__device__ __forceinline__ void mma16816(float* c, const uint32_t* a, const uint32_t* b) {
    asm volatile(
        "mma.sync.aligned.m16n8k16.row.col.f32.f16.f16.f32 "
        "{%0,%1,%2,%3}, {%4,%5,%6,%7}, {%8,%9}, {%0,%1,%2,%3};"
        : "+f"(c[0]), "+f"(c[1]), "+f"(c[2]), "+f"(c[3])
        : "r"(a[0]), "r"(a[1]), "r"(a[2]), "r"(a[3]), "r"(b[0]), "r"(b[1]));
}
#define CPA(s, g) asm volatile("cp.async.cg.shared.global [%0], [%1], 16;" :: "r"(s), "l"(g))
#define CPC()     asm volatile("cp.async.commit_group;" ::: "memory")
#define CPW1()    asm volatile("cp.async.wait_group 1;" ::: "memory")

__device__ __forceinline__ uint32_t packh2(float a, float b) {
    __half2 h = __floats2half2_rn(a, b);
    return *reinterpret_cast<uint32_t*>(&h);
}
__device__ __forceinline__ float ex2f(float x) {
    float y;
    asm("ex2.approx.ftz.f32 %0, %1;" : "=f"(y) : "f"(x));
    return y;
}

// ---------------- fused convert: x + 4 weights + bias concat ----------------
#define XN ((size_t)M_ * D_)        // 4194304
#define WN ((size_t)D_ * D_)        // 1048576

__global__ __launch_bounds__(256)
void cvt_all(const float* __restrict__ x,
             const float* __restrict__ Wq, const float* __restrict__ Wk,
             const float* __restrict__ Wv, const float* __restrict__ Wo,
             const float* __restrict__ bq, const float* __restrict__ bk,
             const float* __restrict__ bv,
             __half* __restrict__ xh, __half* __restrict__ wh,
             float* __restrict__ bias) {
    size_t gid = (size_t)blockIdx.x * 256 + threadIdx.x;
    if (gid < NQKV) {
        int s = (int)(gid >> 10);
        const float* bs = (s == 0) ? bq : (s == 1) ? bk : bv;
        bias[gid] = bs[gid & 1023];
    }
    size_t i = gid * 8;
    const float* src;
    __half* dst;
    if (i < XN) {
        src = x + i; dst = xh + i;
    } else {
        size_t off = i - XN;
        int sel = (int)(off >> 20);
        size_t w = off & (WN - 1);
        src = ((sel == 0) ? Wq : (sel == 1) ? Wk : (sel == 2) ? Wv : Wo) + w;
        dst = wh + off;
    }
    float4 v0 = *(const float4*)(src);
    float4 v1 = *(const float4*)(src + 4);
    __half2 h[4] = { __floats2half2_rn(v0.x, v0.y), __floats2half2_rn(v0.z, v0.w),
                     __floats2half2_rn(v1.x, v1.y), __floats2half2_rn(v1.z, v1.w) };
    *(uint4*)(dst) = *(uint4*)h;
}

// ---------------- fp16 HMMA GEMM ---------------------------------------------
// C[row, col] = sum_k A[row,k] * W[col,k]; col global (W rows concat).
// CTA 128x128, BK=64, 2-stage cp.async, 8 warps (32x64 each).
// QKVMODE: cols<1024 (q) scaled by QSCALE after bias; output fp16 stride ldc.
#define GBM 128
#define GBK 64
#define GSTR 72
#define GBUF (GBM * GSTR)
#define GSMEM_BYTES (4 * GBUF * 2)

template<bool F16OUT, bool QKVMODE>
__global__ __launch_bounds__(256)
void gemm_f16(const __half* __restrict__ A, const __half* __restrict__ Wt,
              const float* __restrict__ bias, void* __restrict__ Cout, int ldc) {
    extern __shared__ __align__(16) __half gsm[];
    __half* As = gsm;
    __half* Ws = gsm + 2 * GBUF;

    const int tid = threadIdx.x;
    const int wid = tid >> 5, lane = tid & 31;
    const int bm = blockIdx.y * GBM, bn = blockIdx.x * GBM;
    const int wm = (wid & 3) * 32, wn = (wid >> 2) * 64;
    const float osc = (QKVMODE && bn < 1024) ? QSCALE : 1.0f;

    float acc[2][8][4];
#pragma unroll
    for (int mt = 0; mt < 2; ++mt)
#pragma unroll
        for (int nt = 0; nt < 8; ++nt)
#pragma unroll
            for (int j = 0; j < 4; ++j) acc[mt][nt][j] = 0.0f;

#define GLOAD(kc, buf) do {                                                        \
    _Pragma("unroll")                                                              \
    for (int i = 0; i < 4; ++i) {                                                  \
        int idx = tid + i * 256; int r = idx >> 3, c = (idx & 7) * 8;              \
        CPA(smem_u32(&As[(buf) * GBUF + r * GSTR + c]),                            \
            A + (size_t)(bm + r) * D_ + (kc) * GBK + c);                           \
        CPA(smem_u32(&Ws[(buf) * GBUF + r * GSTR + c]),                            \
            Wt + (size_t)(bn + r) * D_ + (kc) * GBK + c);                          \
    }                                                                              \
} while (0)

    GLOAD(0, 0);
    CPC();
    int buf = 0;
    for (int kc = 0; kc < D_ / GBK; ++kc) {
        if (kc + 1 < D_ / GBK) GLOAD(kc + 1, buf ^ 1);
        CPC();
        CPW1();
        __syncthreads();
        const __half* Ab = As + buf * GBUF;
        const __half* Wb = Ws + buf * GBUF;
#pragma unroll
        for (int ks = 0; ks < 4; ++ks) {
            uint32_t af[2][4];
#pragma unroll
            for (int mt = 0; mt < 2; ++mt) {
                int row = wm + mt * 16 + (lane & 15);
                int col = ks * 16 + (lane >> 4) * 8;
                ldsm4(af[mt][0], af[mt][1], af[mt][2], af[mt][3],
                      smem_u32(&Ab[row * GSTR + col]));
            }
            uint32_t bf[8][2];
#pragma unroll
            for (int np = 0; np < 4; ++np) {
                int q = lane >> 3;
                int row = wn + np * 16 + (q >> 1) * 8 + (lane & 7);
                int col = ks * 16 + (q & 1) * 8;
                uint32_t r0, r1, r2, r3;
                ldsm4(r0, r1, r2, r3, smem_u32(&Wb[row * GSTR + col]));
                bf[np * 2][0] = r0; bf[np * 2][1] = r1;
                bf[np * 2 + 1][0] = r2; bf[np * 2 + 1][1] = r3;
            }
#pragma unroll
            for (int mt = 0; mt < 2; ++mt)
#pragma unroll
                for (int nt = 0; nt < 8; ++nt)
                    mma16816(acc[mt][nt], af[mt], bf[nt]);
        }
        __syncthreads();
        buf ^= 1;
    }
#undef GLOAD

#pragma unroll
    for (int mt = 0; mt < 2; ++mt) {
        int row = bm + wm + mt * 16 + (lane >> 2);
#pragma unroll
        for (int nt = 0; nt < 8; ++nt) {
            int col = bn + wn + nt * 8 + (lane & 3) * 2;
            float b0 = bias[col], b1 = bias[col + 1];
            float v0 = (acc[mt][nt][0] + b0) * osc, v1 = (acc[mt][nt][1] + b1) * osc;
            float v2 = (acc[mt][nt][2] + b0) * osc, v3 = (acc[mt][nt][3] + b1) * osc;
            if (F16OUT) {
                __half* base = (__half*)Cout;
                *(__half2*)(base + (size_t)row * ldc + col)       = __floats2half2_rn(v0, v1);
                *(__half2*)(base + (size_t)(row + 8) * ldc + col) = __floats2half2_rn(v2, v3);
            } else {
                float* base = (float*)Cout;
                *(float2*)(base + (size_t)row * ldc + col)       = make_float2(v0, v1);
                *(float2*)(base + (size_t)(row + 8) * ldc + col) = make_float2(v2, v3);
            }
        }
    }
}

// ---------------- flash attention, fp16 HMMA, log2-domain softmax -----------
// q pre-scaled by QSCALE; scores are log2-domain -> ex2.approx directly.
// qkv layout: row stride 3072; q at col h*64, k at 1024+h*64, v at 2048+h*64.
#define AQ 128
#define AK 64
#define ASTR 72
#define A_QS   (AQ * ASTR)
#define A_KBUF (AK * ASTR)
#define ASMEM_BYTES ((A_QS + 4 * A_KBUF) * 2 + 2 * AK * 4)

__global__ __launch_bounds__(256)
void flash_f16(const __half* __restrict__ QKV, const int* __restrict__ mask,
               __half* __restrict__ O) {
    extern __shared__ __align__(16) __half asm_[];
    __half* Qs = asm_;
    __half* Ks = asm_ + A_QS;
    __half* Vs = asm_ + A_QS + 2 * A_KBUF;
    int*    msk = (int*)(asm_ + A_QS + 4 * A_KBUF);

    const int b = blockIdx.z, h = blockIdx.y, qt = blockIdx.x;
    const int tid = threadIdx.x, wid = tid >> 5, lane = tid & 31;

    const __half* Qg = QKV + (size_t)(b * S_ + qt * AQ) * NQKV + h * HD_;
    const __half* Kg = QKV + (size_t)(b * S_) * NQKV + 1024 + h * HD_;
    const __half* Vg = QKV + (size_t)(b * S_) * NQKV + 2048 + h * HD_;
    const int* mg = mask + b * S_;

#define KVLOAD(kt, buf) do {                                                          \
    _Pragma("unroll")                                                                 \
    for (int i = 0; i < 2; ++i) {                                                     \
        int idx = tid + i * 256; int r = idx >> 3, c = (idx & 7) * 8;                 \
        CPA(smem_u32(&Ks[(buf) * A_KBUF + r * ASTR + c]),                             \
            Kg + (size_t)((kt) * AK + r) * NQKV + c);                                 \
        CPA(smem_u32(&Vs[(buf) * A_KBUF + r * ASTR + c]),                             \
            Vg + (size_t)((kt) * AK + r) * NQKV + c);                                 \
    }                                                                                 \
    if (tid < 16) CPA(smem_u32(&msk[(buf) * AK + tid * 4]), mg + (kt) * AK + tid * 4);\
} while (0)

#pragma unroll
    for (int i = 0; i < 4; ++i) {
        int idx = tid + i * 256; int r = idx >> 3, c = (idx & 7) * 8;
        CPA(smem_u32(&Qs[r * ASTR + c]), Qg + (size_t)r * NQKV + c);
    }
    KVLOAD(0, 0);
    CPC();

    float m0 = -1e30f, m1 = -1e30f, l0 = 0.0f, l1 = 0.0f;
    float oacc[8][4];
#pragma unroll
    for (int nt = 0; nt < 8; ++nt)
#pragma unroll
        for (int j = 0; j < 4; ++j) oacc[nt][j] = 0.0f;
    uint32_t qf[4][4];

    int buf = 0;
    for (int kt = 0; kt < S_ / AK; ++kt) {
        if (kt + 1 < S_ / AK) KVLOAD(kt + 1, buf ^ 1);
        CPC();
        CPW1();
        __syncthreads();
        if (kt == 0) {
#pragma unroll
            for (int ks = 0; ks < 4; ++ks) {
                int row = wid * 16 + (lane & 15);
                int col = ks * 16 + (lane >> 4) * 8;
                ldsm4(qf[ks][0], qf[ks][1], qf[ks][2], qf[ks][3],
                      smem_u32(&Qs[row * ASTR + col]));
            }
        }

        // ---- S = Q K^T (already log2-domain: q pre-scaled) ----
        float sacc[8][4];
#pragma unroll
        for (int nt = 0; nt < 8; ++nt)
#pragma unroll
            for (int j = 0; j < 4; ++j) sacc[nt][j] = 0.0f;
        const __half* Kb = Ks + buf * A_KBUF;
        const __half* Vb = Vs + buf * A_KBUF;
        const int* mb = msk + buf * AK;
#pragma unroll
        for (int ks = 0; ks < 4; ++ks) {
            uint32_t bfr[8][2];
#pragma unroll
            for (int np = 0; np < 4; ++np) {
                int q = lane >> 3;
                int row = np * 16 + (q >> 1) * 8 + (lane & 7);
                int col = ks * 16 + (q & 1) * 8;
                uint32_t r0, r1, r2, r3;
                ldsm4(r0, r1, r2, r3, smem_u32(&Kb[row * ASTR + col]));
                bfr[np * 2][0] = r0; bfr[np * 2][1] = r1;
                bfr[np * 2 + 1][0] = r2; bfr[np * 2 + 1][1] = r3;
            }
#pragma unroll
            for (int nt = 0; nt < 8; ++nt) mma16816(sacc[nt], qf[ks], bfr[nt]);
        }

        // ---- mask + online softmax (base 2) ----
        const int cc = (lane & 3) * 2;
#pragma unroll
        for (int nt = 0; nt < 8; ++nt) {
            int col = nt * 8 + cc;
            float ma  = mb[col]     ? 0.0f : -1e9f;
            float mbv = mb[col + 1] ? 0.0f : -1e9f;
            sacc[nt][0] += ma;  sacc[nt][1] += mbv;
            sacc[nt][2] += ma;  sacc[nt][3] += mbv;
        }
        float rx0 = -1e30f, rx1 = -1e30f;
#pragma unroll
        for (int nt = 0; nt < 8; ++nt) {
            rx0 = fmaxf(rx0, fmaxf(sacc[nt][0], sacc[nt][1]));
            rx1 = fmaxf(rx1, fmaxf(sacc[nt][2], sacc[nt][3]));
        }
        rx0 = fmaxf(rx0, __shfl_xor_sync(0xffffffffu, rx0, 1));
        rx0 = fmaxf(rx0, __shfl_xor_sync(0xffffffffu, rx0, 2));
        rx1 = fmaxf(rx1, __shfl_xor_sync(0xffffffffu, rx1, 1));
        rx1 = fmaxf(rx1, __shfl_xor_sync(0xffffffffu, rx1, 2));
        float mn0 = fmaxf(m0, rx0), mn1 = fmaxf(m1, rx1);
        float cor0 = ex2f(m0 - mn0), cor1 = ex2f(m1 - mn1);
        m0 = mn0; m1 = mn1;
        float rs0 = 0.0f, rs1 = 0.0f;
#pragma unroll
        for (int nt = 0; nt < 8; ++nt) {
            sacc[nt][0] = ex2f(sacc[nt][0] - mn0);
            sacc[nt][1] = ex2f(sacc[nt][1] - mn0);
            sacc[nt][2] = ex2f(sacc[nt][2] - mn1);
            sacc[nt][3] = ex2f(sacc[nt][3] - mn1);
            rs0 += sacc[nt][0] + sacc[nt][1];
            rs1 += sacc[nt][2] + sacc[nt][3];
        }
        rs0 += __shfl_xor_sync(0xffffffffu, rs0, 1);
        rs0 += __shfl_xor_sync(0xffffffffu, rs0, 2);
        rs1 += __shfl_xor_sync(0xffffffffu, rs1, 1);
        rs1 += __shfl_xor_sync(0xffffffffu, rs1, 2);
        l0 = l0 * cor0 + rs0;
        l1 = l1 * cor1 + rs1;
#pragma unroll
        for (int nt = 0; nt < 8; ++nt) {
            oacc[nt][0] *= cor0; oacc[nt][1] *= cor0;
            oacc[nt][2] *= cor1; oacc[nt][3] *= cor1;
        }

        // ---- O += P V ----
#pragma unroll
        for (int ks = 0; ks < 4; ++ks) {
            uint32_t pa[4];
            pa[0] = packh2(sacc[2 * ks][0],     sacc[2 * ks][1]);
            pa[1] = packh2(sacc[2 * ks][2],     sacc[2 * ks][3]);
            pa[2] = packh2(sacc[2 * ks + 1][0], sacc[2 * ks + 1][1]);
            pa[3] = packh2(sacc[2 * ks + 1][2], sacc[2 * ks + 1][3]);
            uint32_t bfr[8][2];
#pragma unroll
            for (int np = 0; np < 4; ++np) {
                int q = lane >> 3;
                int row = ks * 16 + (q & 1) * 8 + (lane & 7);
                int col = np * 16 + (q >> 1) * 8;
                uint32_t r0, r1, r2, r3;
                ldsm4t(r0, r1, r2, r3, smem_u32(&Vb[row * ASTR + col]));
                bfr[np * 2][0] = r0; bfr[np * 2][1] = r1;
                bfr[np * 2 + 1][0] = r2; bfr[np * 2 + 1][1] = r3;
            }
#pragma unroll
            for (int nt = 0; nt < 8; ++nt) mma16816(oacc[nt], pa, bfr[nt]);
        }
        __syncthreads();
        buf ^= 1;
    }
#undef KVLOAD

    float li0 = 1.0f / l0, li1 = 1.0f / l1;
    __half* Og = O + (size_t)(b * S_ + qt * AQ + wid * 16) * D_ + h * HD_;
    int r0 = lane >> 2;
#pragma unroll
    for (int nt = 0; nt < 8; ++nt) {
        int col = nt * 8 + (lane & 3) * 2;
        *(__half2*)(Og + (size_t)r0 * D_ + col) =
            __floats2half2_rn(oacc[nt][0] * li0, oacc[nt][1] * li0);
        *(__half2*)(Og + (size_t)(r0 + 8) * D_ + col) =
            __floats2half2_rn(oacc[nt][2] * li1, oacc[nt][3] * li1);
    }
}

// ---------------------------- launch ---------------------------------------
extern "C" void kernel_launch(void* const* d_in, const int* in_sizes, int n_in,
                              void* d_out, int out_size) {
    const float* x    = (const float*)d_in[0];
    const int*   mask = (const int*)d_in[1];
    const float* Wq   = (const float*)d_in[2];
    const float* bq   = (const float*)d_in[3];
    const float* Wk   = (const float*)d_in[4];
    const float* bk   = (const float*)d_in[5];
    const float* Wv   = (const float*)d_in[6];
    const float* bv   = (const float*)d_in[7];
    const float* Wo   = (const float*)d_in[8];
    const float* bo   = (const float*)d_in[9];
    float* out = (float*)d_out;

    __half *xh, *wh, *qkv, *ah;
    float* bias;
    cudaGetSymbolAddress((void**)&xh,   g_xh);
    cudaGetSymbolAddress((void**)&wh,   g_wh);
    cudaGetSymbolAddress((void**)&qkv,  g_qkv);
    cudaGetSymbolAddress((void**)&ah,   g_ah);
    cudaGetSymbolAddress((void**)&bias, g_bias);

    cudaFuncSetAttribute(gemm_f16<true, true>,   cudaFuncAttributeMaxDynamicSharedMemorySize, GSMEM_BYTES);
    cudaFuncSetAttribute(gemm_f16<false, false>, cudaFuncAttributeMaxDynamicSharedMemorySize, GSMEM_BYTES);
    cudaFuncSetAttribute(flash_f16,              cudaFuncAttributeMaxDynamicSharedMemorySize, ASMEM_BYTES);

    // 1: convert everything
    cvt_all<<<(int)((XN + 4 * WN) / 8 / 256), 256>>>(x, Wq, Wk, Wv, Wo, bq, bk, bv,
                                                     xh, wh, bias);
    // 2: fused QKV projection (q pre-scaled into log2 domain)
    dim3 qgrid(NQKV / 128, M_ / 128);   // (24, 32)
    gemm_f16<true, true><<<qgrid, 256, GSMEM_BYTES>>>(xh, wh, bias, qkv, NQKV);

    // 3: flash attention
    dim3 agrid(S_ / AQ, H_, B_);        // (16, 16, 2)
    flash_f16<<<agrid, 256, ASMEM_BYTES>>>(qkv, mask, ah);

    // 4: output projection (fp32 out)
    dim3 ogrid(D_ / 128, M_ / 128);     // (8, 32)
    gemm_f16<false, false><<<ogrid, 256, GSMEM_BYTES>>>(ah, wh + 3 * WN, bo, out, D_);
    (void)n_in; (void)in_sizes; (void)out_size;
}